// round 3
// baseline (speedup 1.0000x reference)
#include <cuda_runtime.h>

#define NGROUPS 8
#define THREADS 256
#define ITER 4                        // elements per thread per tile
#define TILE (THREADS * ITER)         // 1024 rows per tile
#define NBLOCKS 1024
#define MAX_BLOCKS 2048

// Scratch (no allocations allowed). g_part fully overwritten each run;
// g_counter reset to 0 by the last block (deterministic across replays).
__device__ float    g_part[MAX_BLOCKS * 2 * NGROUPS];
__device__ unsigned g_counter = 0;

__device__ __forceinline__ void block_reduce_16(float* s, float* c,
                                                float* red /* [THREADS/32][16] */) {
#pragma unroll
    for (int j = 0; j < NGROUPS; j++) {
#pragma unroll
        for (int o = 16; o > 0; o >>= 1) {
            s[j] += __shfl_down_sync(0xffffffffu, s[j], o);
            c[j] += __shfl_down_sync(0xffffffffu, c[j], o);
        }
    }
    int lane = threadIdx.x & 31;
    int warp = threadIdx.x >> 5;
    if (lane == 0) {
#pragma unroll
        for (int j = 0; j < NGROUPS; j++) {
            red[warp * 16 + j]           = s[j];
            red[warp * 16 + NGROUPS + j] = c[j];
        }
    }
    __syncthreads();
    if (threadIdx.x < 2 * NGROUPS) {
        float t = 0.0f;
#pragma unroll
        for (int w = 0; w < THREADS / 32; w++) t += red[w * 16 + threadIdx.x];
        red[threadIdx.x] = t;   // result lives in red[0..15]
    }
    __syncthreads();
}

__global__ __launch_bounds__(THREADS, 6) void fused_kernel(
    const float* __restrict__ in, const int* __restrict__ tgt,
    const int* __restrict__ grp, float* __restrict__ out, int n)
{
    __shared__ float red[(THREADS / 32) * 16];
    __shared__ bool  is_last;

    float s[NGROUPS], c[NGROUPS];
#pragma unroll
    for (int j = 0; j < NGROUPS; j++) { s[j] = 0.0f; c[j] = 0.0f; }

    int ntiles = (n + TILE - 1) / TILE;

    for (int tile = blockIdx.x; tile < ntiles; tile += gridDim.x) {
        int base = tile * TILE + threadIdx.x;

        // Phase A: coalesced index loads (lanes map to consecutive rows)
        int t[ITER], g[ITER];
#pragma unroll
        for (int k = 0; k < ITER; k++) {
            int i = base + k * THREADS;
            bool ok = (i < n);
            t[k] = ok ? __ldcs(tgt + i) : 0;
            g[k] = ok ? __ldcs(grp + i) : -1;
        }

        // Phase B: gathers — adjacent lanes share a 128B line (rows are 64B)
        float v[ITER];
#pragma unroll
        for (int k = 0; k < ITER; k++) {
            int i = base + k * THREADS;
            v[k] = (i < n) ? __ldcs(in + ((size_t)i << 4) + t[k]) : 0.0f;
        }

        // Phase C: predicated per-group accumulation
#pragma unroll
        for (int k = 0; k < ITER; k++) {
            float e = fabsf(1.0f - v[k]);
#pragma unroll
            for (int j = 0; j < NGROUPS; j++) {
                bool m = (g[k] == j);
                s[j] += m ? e : 0.0f;
                c[j] += m ? 1.0f : 0.0f;    // exact in f32 (< 2^24)
            }
        }
    }

    block_reduce_16(s, c, red);

    if (threadIdx.x < 2 * NGROUPS)
        g_part[blockIdx.x * 2 * NGROUPS + threadIdx.x] = red[threadIdx.x];
    __syncthreads();

    if (threadIdx.x == 0) {
        __threadfence();
        unsigned v = atomicAdd(&g_counter, 1u);
        is_last = (v == gridDim.x - 1);
    }
    __syncthreads();
    if (!is_last) return;

    // Final reduction over per-block partials (L2-hot)
    float fs[NGROUPS], fc[NGROUPS];
#pragma unroll
    for (int j = 0; j < NGROUPS; j++) { fs[j] = 0.0f; fc[j] = 0.0f; }
    for (int b = threadIdx.x; b < gridDim.x; b += THREADS) {
#pragma unroll
        for (int j = 0; j < NGROUPS; j++) {
            fs[j] += g_part[b * 2 * NGROUPS + j];
            fc[j] += g_part[b * 2 * NGROUPS + NGROUPS + j];
        }
    }
    __syncthreads();
    block_reduce_16(fs, fc, red);

    if (threadIdx.x == 0) {
        float msum = 0.0f;
#pragma unroll
        for (int j = 0; j < NGROUPS; j++) {
            float cnt = red[NGROUPS + j];
            msum += (cnt > 0.0f) ? (red[j] / cnt) : 0.0f;
        }
        out[0] = fabsf(0.5f - msum * (1.0f / NGROUPS));
        g_counter = 0;   // reset for next graph replay
    }
}

extern "C" void kernel_launch(void* const* d_in, const int* in_sizes, int n_in,
                              void* d_out, int out_size) {
    const float* in  = (const float*)d_in[0];
    const int*   tgt = (const int*)d_in[1];
    const int*   grp = (const int*)d_in[2];
    float*       out = (float*)d_out;
    int n = in_sizes[1];  // N rows

    int ntiles = (n + TILE - 1) / TILE;
    int blocks = ntiles < NBLOCKS ? ntiles : NBLOCKS;
    if (blocks > MAX_BLOCKS) blocks = MAX_BLOCKS;
    if (blocks < 1) blocks = 1;
    fused_kernel<<<blocks, THREADS>>>(in, tgt, grp, out, n);
}

// round 5
// speedup vs baseline: 1.0309x; 1.0309x over previous
#include <cuda_runtime.h>

#define NGROUPS 8
#define THREADS 256
#define ITER 8                        // rows per thread per tile
#define TILE (THREADS * ITER)         // 2048 rows per block-tile
#define NBLOCKS 2048
#define MAX_BLOCKS 2048

// Scratch (no allocations allowed). g_part fully overwritten each run;
// g_counter reset to 0 by the last block (deterministic across replays).
__device__ float    g_part[MAX_BLOCKS * 2 * NGROUPS];
__device__ unsigned g_counter = 0;

__device__ __forceinline__ void block_reduce_16(float* s, float* c,
                                                float* red /* [THREADS/32][16] */) {
#pragma unroll
    for (int j = 0; j < NGROUPS; j++) {
#pragma unroll
        for (int o = 16; o > 0; o >>= 1) {
            s[j] += __shfl_down_sync(0xffffffffu, s[j], o);
            c[j] += __shfl_down_sync(0xffffffffu, c[j], o);
        }
    }
    int lane = threadIdx.x & 31;
    int warp = threadIdx.x >> 5;
    if (lane == 0) {
#pragma unroll
        for (int j = 0; j < NGROUPS; j++) {
            red[warp * 16 + j]           = s[j];
            red[warp * 16 + NGROUPS + j] = c[j];
        }
    }
    __syncthreads();
    if (threadIdx.x < 2 * NGROUPS) {
        float t = 0.0f;
#pragma unroll
        for (int w = 0; w < THREADS / 32; w++) t += red[w * 16 + threadIdx.x];
        red[threadIdx.x] = t;   // result lives in red[0..15]
    }
    __syncthreads();
}

__global__ __launch_bounds__(THREADS) void fused_kernel(
    const float* __restrict__ in, const int* __restrict__ tgt,
    const int* __restrict__ grp, float* __restrict__ out, int n)
{
    __shared__ int   s_tgt[TILE];
    __shared__ int   s_grp[TILE];
    __shared__ float red[(THREADS / 32) * 16];
    __shared__ bool  is_last;

    float s[NGROUPS], c[NGROUPS];
#pragma unroll
    for (int j = 0; j < NGROUPS; j++) { s[j] = 0.0f; c[j] = 0.0f; }

    int ntiles = (n + TILE - 1) / TILE;
    int tid = threadIdx.x;

    for (int tile = blockIdx.x; tile < ntiles; tile += gridDim.x) {
        int base = tile * TILE;

        // ---- Stage indices into smem: independent vectorized loads, no
        // consumer until after the barrier. Breaks the index->gather chain.
        if (base + TILE <= n) {
            const int4* t4 = (const int4*)(tgt + base);
            const int4* g4 = (const int4*)(grp + base);
#pragma unroll
            for (int j = 0; j < TILE / 4 / THREADS; j++) {   // 2 each
                ((int4*)s_tgt)[tid + j * THREADS] = __ldcs(t4 + tid + j * THREADS);
                ((int4*)s_grp)[tid + j * THREADS] = __ldcs(g4 + tid + j * THREADS);
            }
        } else {
            for (int m = tid; m < TILE; m += THREADS) {
                bool ok = (base + m < n);
                s_tgt[m] = ok ? tgt[base + m] : 0;
                s_grp[m] = ok ? -1 - (-1 - grp[base + m]) : -1;  // = grp or -1
                if (!ok) s_grp[m] = -1;
            }
        }
        __syncthreads();

        // ---- Gathers: addresses come from smem (29cy), all 8 LDGs issue
        // back-to-back => MLP=8/thread, 256/warp-group; DRAM queue stays full.
        float v[ITER];
#pragma unroll
        for (int k = 0; k < ITER; k++) {
            int m = tid + k * THREADS;            // lanes consecutive: 2 rows/128B line
            int i = base + m;
            int t = s_tgt[m];
            v[k] = (i < n) ? __ldcs(in + ((size_t)i << 4) + t) : 0.0f;
        }

        // ---- Accumulate
#pragma unroll
        for (int k = 0; k < ITER; k++) {
            int g = s_grp[tid + k * THREADS];
            float e = fabsf(1.0f - v[k]);
#pragma unroll
            for (int j = 0; j < NGROUPS; j++) {
                bool m = (g == j);
                s[j] += m ? e : 0.0f;
                c[j] += m ? 1.0f : 0.0f;          // exact in f32 (< 2^24)
            }
        }
        __syncthreads();   // protect smem before next tile overwrites
    }

    block_reduce_16(s, c, red);

    if (threadIdx.x < 2 * NGROUPS)
        g_part[blockIdx.x * 2 * NGROUPS + threadIdx.x] = red[threadIdx.x];
    __syncthreads();

    if (threadIdx.x == 0) {
        __threadfence();
        unsigned v = atomicAdd(&g_counter, 1u);
        is_last = (v == gridDim.x - 1);
    }
    __syncthreads();
    if (!is_last) return;

    // Final reduction over per-block partials (L2-hot)
    float fs[NGROUPS], fc[NGROUPS];
#pragma unroll
    for (int j = 0; j < NGROUPS; j++) { fs[j] = 0.0f; fc[j] = 0.0f; }
    for (int b = threadIdx.x; b < gridDim.x; b += THREADS) {
#pragma unroll
        for (int j = 0; j < NGROUPS; j++) {
            fs[j] += g_part[b * 2 * NGROUPS + j];
            fc[j] += g_part[b * 2 * NGROUPS + NGROUPS + j];
        }
    }
    __syncthreads();
    block_reduce_16(fs, fc, red);

    if (threadIdx.x == 0) {
        float msum = 0.0f;
#pragma unroll
        for (int j = 0; j < NGROUPS; j++) {
            float cnt = red[NGROUPS + j];
            msum += (cnt > 0.0f) ? (red[j] / cnt) : 0.0f;
        }
        out[0] = fabsf(0.5f - msum * (1.0f / NGROUPS));
        g_counter = 0;   // reset for next graph replay
    }
}

extern "C" void kernel_launch(void* const* d_in, const int* in_sizes, int n_in,
                              void* d_out, int out_size) {
    const float* in  = (const float*)d_in[0];
    const int*   tgt = (const int*)d_in[1];
    const int*   grp = (const int*)d_in[2];
    float*       out = (float*)d_out;
    int n = in_sizes[1];  // N rows

    int ntiles = (n + TILE - 1) / TILE;
    int blocks = ntiles < NBLOCKS ? ntiles : NBLOCKS;
    if (blocks > MAX_BLOCKS) blocks = MAX_BLOCKS;
    if (blocks < 1) blocks = 1;
    fused_kernel<<<blocks, THREADS>>>(in, tgt, grp, out, n);
}